// round 1
// baseline (speedup 1.0000x reference)
#include <cuda_runtime.h>
#include <math.h>

// ---------------------------------------------------------------------------
// SimpleConvGRU on GB300 — round 0: direct fp32 convolution baseline.
// B=16, T=28, H=W=32, CIN=24, F=64, C1=32, 3x3 SAME convs, NHWC / HWIO.
// ---------------------------------------------------------------------------

#define B_ 16
#define T_ 28
#define H_ 32
#define W_ 32
#define HW_ 1024
#define F_ 64

// [2][B][T][HW][192] gate buffers (reused across layers)
__device__ float g_XG[(size_t)2 * B_ * T_ * HW_ * 192];
// Layer outputs [B][T][HW][128] (fwd ch 0..63, bwd ch 64..127)
__device__ float g_Y0[(size_t)B_ * T_ * HW_ * 128];
__device__ float g_Y1[(size_t)B_ * T_ * HW_ * 128];
// Per-step temporaries
__device__ float g_GH[(size_t)2 * B_ * HW_ * 128];
__device__ float g_Z [(size_t)2 * B_ * HW_ * 64];
__device__ float g_RH[(size_t)2 * B_ * HW_ * 64];
// Concat buffer [448][HW][256] and conv1 output [448][HW][32]
__device__ float g_XC[(size_t)B_ * T_ * HW_ * 256];
__device__ float g_H1[(size_t)B_ * T_ * HW_ * 32];

#define XG_DIRSTRIDE ((long)B_ * T_ * HW_ * 192)

__device__ __forceinline__ float sigmoidf_(float x) {
    return 1.0f / (1.0f + expf(-x));
}

// ---------------------------------------------------------------------------
// Generic 3x3 SAME conv, NHWC. Block = 256 thr = 8 warps; each warp does one
// 8-pixel row segment; lane -> output channel within a 32-channel group.
// Each thread accumulates 8 pixels (amortizes weight loads 24 FMA / 13 loads).
// grid = (W/8, H/8, nDirs*nImg*(Cout/32)).
// ---------------------------------------------------------------------------
__global__ __launch_bounds__(256) void conv3x3_kernel(
    const float* __restrict__ in0, const float* __restrict__ in1,
    long inImgStride, int inCstride, int Cin,
    const float* __restrict__ w0, const float* __restrict__ w1,
    int wCstride, int wCoff,
    const float* __restrict__ bias0, const float* __restrict__ bias1,
    float* __restrict__ out0, float* __restrict__ out1,
    long outImgStride, int outCstride, int outCoff,
    int Cout, int nImg)
{
    int CG = Cout >> 5;
    int perDir = nImg * CG;
    int z = blockIdx.z;
    int dir = z / perDir;
    int rem = z - dir * perDir;
    int img = rem / CG;
    int cg  = rem - img * CG;

    const float* in   = dir ? in1 : in0;
    const float* wt   = dir ? w1  : w0;
    const float* bias = dir ? bias1 : bias0;
    float*       out  = dir ? out1 : out0;

    int lane = threadIdx.x & 31;
    int warp = threadIdx.x >> 5;
    int cout = cg * 32 + lane;
    int y0 = blockIdx.y * 8 + warp;
    int x0 = blockIdx.x * 8;

    const float* inImg = in + (long)img * inImgStride;
    const float* wBase = wt + wCoff + cout;

    float acc[8];
    float bv = bias ? __ldg(bias + cout) : 0.0f;
#pragma unroll
    for (int p = 0; p < 8; p++) acc[p] = bv;

    bool okx[10];
#pragma unroll
    for (int q = 0; q < 10; q++) {
        int ix = x0 - 1 + q;
        okx[q] = (ix >= 0 && ix < W_);
    }

    for (int ky = 0; ky < 3; ky++) {
        int iy = y0 + ky - 1;
        bool rowok = (iy >= 0 && iy < H_);
        const float* rowPtr = inImg + ((long)iy * W_ + (x0 - 1)) * inCstride;
        const float* wRow = wBase + (long)(ky * 3) * Cin * wCstride;

        const float* pq[10];
#pragma unroll
        for (int q = 0; q < 10; q++) pq[q] = rowPtr + (long)q * inCstride;

#pragma unroll 4
        for (int cin = 0; cin < Cin; cin++) {
            float v[10];
#pragma unroll
            for (int q = 0; q < 10; q++)
                v[q] = (rowok && okx[q]) ? __ldg(pq[q] + cin) : 0.0f;
            float wv0 = __ldg(wRow + (long)cin * wCstride);
            float wv1 = __ldg(wRow + (long)(Cin + cin) * wCstride);
            float wv2 = __ldg(wRow + (long)(2 * Cin + cin) * wCstride);
#pragma unroll
            for (int p = 0; p < 8; p++)
                acc[p] += wv0 * v[p] + wv1 * v[p + 1] + wv2 * v[p + 2];
        }
    }

    float* outP = out + (long)img * outImgStride
                + ((long)y0 * W_ + x0) * outCstride + outCoff + cout;
#pragma unroll
    for (int p = 0; p < 8; p++) outP[(long)p * outCstride] = acc[p];
}

// ---------------------------------------------------------------------------
// Elementwise: z = sig(g0+gh0), r = sig(g1+gh1), RH = r*h_prev. Both dirs.
// grid over 2*B*HW*16 float4 lanes.
// ---------------------------------------------------------------------------
__global__ __launch_bounds__(256) void zrh_kernel(
    const float* __restrict__ xg0, const float* __restrict__ xg1, // + t*HW*192
    const float* __restrict__ gh,                                  // [2][B][HW][128]
    const float* __restrict__ h0, const float* __restrict__ h1,    // + tprev*HW*128 + dirOff
    float* __restrict__ Z, float* __restrict__ RH,
    int hValid)
{
    int idx = blockIdx.x * blockDim.x + threadIdx.x;
    const int total = 2 * B_ * HW_ * 16;
    if (idx >= total) return;
    int c4  = idx & 15;
    int t1  = idx >> 4;
    int yx  = t1 & (HW_ - 1);
    int t2  = t1 >> 10;
    int b   = t2 & 15;
    int dir = t2 >> 4;
    int c = c4 * 4;

    const float* xg = (dir ? xg1 : xg0) + (long)b * ((long)T_ * HW_ * 192) + (long)yx * 192;
    float4 gz = *(const float4*)(xg + c);
    float4 gr = *(const float4*)(xg + 64 + c);

    float4 a0 = make_float4(0.f, 0.f, 0.f, 0.f);
    float4 a1 = a0;
    float4 hv = a0;
    if (hValid) {
        const float* ghp = gh + ((long)(dir * B_ + b) * HW_ + yx) * 128;
        a0 = *(const float4*)(ghp + c);
        a1 = *(const float4*)(ghp + 64 + c);
        const float* hp = (dir ? h1 : h0) + (long)b * ((long)T_ * HW_ * 128) + (long)yx * 128 + c;
        hv = *(const float4*)hp;
    }
    float4 zv, rv;
    zv.x = sigmoidf_(gz.x + a0.x); zv.y = sigmoidf_(gz.y + a0.y);
    zv.z = sigmoidf_(gz.z + a0.z); zv.w = sigmoidf_(gz.w + a0.w);
    rv.x = sigmoidf_(gr.x + a1.x); rv.y = sigmoidf_(gr.y + a1.y);
    rv.z = sigmoidf_(gr.z + a1.z); rv.w = sigmoidf_(gr.w + a1.w);

    long zo = ((long)(dir * B_ + b) * HW_ + yx) * 64 + c;
    *(float4*)(Z + zo) = zv;
    float4 rh;
    rh.x = rv.x * hv.x; rh.y = rv.y * hv.y; rh.z = rv.z * hv.z; rh.w = rv.w * hv.w;
    *(float4*)(RH + zo) = rh;
}

// ---------------------------------------------------------------------------
// Candidate conv (RH * wh_h, 64->64) fused with tanh + GRU blend epilogue.
// grid = (4,4,64): dir(2) x img(16) x coutGroup(2).
// ---------------------------------------------------------------------------
__global__ __launch_bounds__(256) void conv_blend_kernel(
    const float* __restrict__ RH,
    const float* __restrict__ w0, const float* __restrict__ w1,
    const float* __restrict__ xg0, const float* __restrict__ xg1, // + t*HW*192 + 128
    const float* __restrict__ h0, const float* __restrict__ h1,   // + tprev*HW*128 + dirOff
    const float* __restrict__ Z,
    float* __restrict__ yo0, float* __restrict__ yo1,             // + t*HW*128 + dirOff
    int hValid)
{
    int z = blockIdx.z;
    int dir = z >> 5;
    int rem = z & 31;
    int img = rem >> 1;
    int cg  = rem & 1;
    int lane = threadIdx.x & 31;
    int warp = threadIdx.x >> 5;
    int cout = cg * 32 + lane;
    int y0 = blockIdx.y * 8 + warp;
    int x0 = blockIdx.x * 8;

    const float* in = RH + (long)(dir * B_ + img) * HW_ * 64;
    const float* wt = (dir ? w1 : w0) + 128 + cout;   // wh_h = wh[..., 128:]

    float acc[8];
#pragma unroll
    for (int p = 0; p < 8; p++) acc[p] = 0.0f;

    bool okx[10];
#pragma unroll
    for (int q = 0; q < 10; q++) {
        int ix = x0 - 1 + q;
        okx[q] = (ix >= 0 && ix < W_);
    }

    for (int ky = 0; ky < 3; ky++) {
        int iy = y0 + ky - 1;
        bool rowok = (iy >= 0 && iy < H_);
        const float* rowPtr = in + ((long)iy * W_ + (x0 - 1)) * 64;
        const float* wRow = wt + (long)(ky * 3) * 64 * 192;
#pragma unroll 4
        for (int cin = 0; cin < 64; cin++) {
            float v[10];
#pragma unroll
            for (int q = 0; q < 10; q++)
                v[q] = (rowok && okx[q]) ? __ldg(rowPtr + q * 64 + cin) : 0.0f;
            float wv0 = __ldg(wRow + cin * 192);
            float wv1 = __ldg(wRow + (64 + cin) * 192);
            float wv2 = __ldg(wRow + (128 + cin) * 192);
#pragma unroll
            for (int p = 0; p < 8; p++)
                acc[p] += wv0 * v[p] + wv1 * v[p + 1] + wv2 * v[p + 2];
        }
    }

    const float* xg = (dir ? xg1 : xg0) + (long)img * ((long)T_ * HW_ * 192);
    const float* hp = (dir ? h1  : h0 ) + (long)img * ((long)T_ * HW_ * 128);
    const float* zp = Z + (long)(dir * B_ + img) * HW_ * 64;
    float* yo = (dir ? yo1 : yo0) + (long)img * ((long)T_ * HW_ * 128);
    int pixBase = y0 * W_ + x0;
#pragma unroll
    for (int p = 0; p < 8; p++) {
        int pix = pixBase + p;
        float g3 = xg[(long)pix * 192 + cout];
        float zv = zp[(long)pix * 64 + cout];
        float hv = hValid ? hp[(long)pix * 128 + cout] : 0.0f;
        float cand = tanhf(g3 + acc[p]);
        yo[(long)pix * 128 + cout] = zv * hv + (1.0f - zv) * cand;
    }
}

__global__ __launch_bounds__(256) void add_kernel(
    float* __restrict__ a, const float* __restrict__ b, long n4)
{
    long i = (long)blockIdx.x * blockDim.x + threadIdx.x;
    if (i >= n4) return;
    float4 va = ((float4*)a)[i];
    float4 vb = ((const float4*)b)[i];
    va.x += vb.x; va.y += vb.y; va.z += vb.z; va.w += vb.w;
    ((float4*)a)[i] = va;
}

__global__ __launch_bounds__(256) void concat_kernel(
    const float* __restrict__ xr, const float* __restrict__ x0,
    float* __restrict__ xc, long nPix)
{
    long i = (long)blockIdx.x * blockDim.x + threadIdx.x;
    if (i >= nPix * 64) return;
    long pix = i >> 6;
    int  c4  = (int)(i & 63);
    int  c   = c4 * 4;
    float4 v;
    if (c < 128) v = *(const float4*)(xr + pix * 128 + c);
    else         v = *(const float4*)(x0 + pix * 128 + (c - 128));
    *(float4*)(xc + pix * 256 + c) = v;
}

__global__ __launch_bounds__(256) void out1x1_kernel(
    const float* __restrict__ h, const float* __restrict__ w,
    const float* __restrict__ b, float* __restrict__ out, int n)
{
    int i = blockIdx.x * blockDim.x + threadIdx.x;
    if (i >= n) return;
    const float* hp = h + (long)i * 32;
    float s = __ldg(b);
#pragma unroll
    for (int c = 0; c < 32; c++) s += hp[c] * __ldg(w + c);
    out[i] = fmaxf(s, 0.0f);
}

// ---------------------------------------------------------------------------
// Host side
// ---------------------------------------------------------------------------
static void conv_launch(const float* in0, const float* in1, long inImgStride, int inCstride, int Cin,
                        const float* w0, const float* w1, int wCstride, int wCoff,
                        const float* bias0, const float* bias1,
                        float* out0, float* out1, long outImgStride, int outCstride, int outCoff,
                        int Cout, int nImg, int nDirs)
{
    dim3 grid(4, 4, (unsigned)(nDirs * nImg * (Cout / 32)));
    conv3x3_kernel<<<grid, 256>>>(in0, in1, inImgStride, inCstride, Cin,
                                  w0, w1, wCstride, wCoff, bias0, bias1,
                                  out0, out1, outImgStride, outCstride, outCoff,
                                  Cout, nImg);
}

static void run_layer(float* XG, float* Y, float* GH, float* Z, float* RH,
                      const float* whF, const float* whB)
{
    for (int i = 0; i < T_; i++) {
        int tf = i, tb = T_ - 1 - i;
        int hValid = (i > 0);
        const float* hF = Y + (long)(tf - 1) * HW_ * 128;        // fwd h_prev (ch 0..63)
        const float* hB = Y + (long)(tb + 1) * HW_ * 128 + 64;   // bwd h_prev (ch 64..127)
        if (hValid) {
            // gh = conv(h_prev, wh_zr) 64->128 for both directions
            conv_launch(hF, hB, (long)T_ * HW_ * 128, 128, 64,
                        whF, whB, 192, 0, nullptr, nullptr,
                        GH, GH + (long)B_ * HW_ * 128, (long)HW_ * 128, 128, 0,
                        128, B_, 2);
        }
        zrh_kernel<<<2048, 256>>>(XG + (long)tf * HW_ * 192,
                                  XG + XG_DIRSTRIDE + (long)tb * HW_ * 192,
                                  GH, hF, hB, Z, RH, hValid);
        conv_blend_kernel<<<dim3(4, 4, 64), 256>>>(RH, whF, whB,
            XG + (long)tf * HW_ * 192 + 128,
            XG + XG_DIRSTRIDE + (long)tb * HW_ * 192 + 128,
            hF, hB, Z,
            Y + (long)tf * HW_ * 128,
            Y + (long)tb * HW_ * 128 + 64,
            hValid);
    }
}

extern "C" void kernel_launch(void* const* d_in, const int* in_sizes, int n_in,
                              void* d_out, int out_size)
{
    (void)in_sizes; (void)n_in; (void)out_size;
    const float* x       = (const float*)d_in[0];
    const float* wx_f0   = (const float*)d_in[1];
    const float* wh_f0   = (const float*)d_in[2];
    const float* b_f0    = (const float*)d_in[3];
    const float* wx_b0   = (const float*)d_in[4];
    const float* wh_b0   = (const float*)d_in[5];
    const float* b_b0    = (const float*)d_in[6];
    const float* wx_f1   = (const float*)d_in[7];
    const float* wh_f1   = (const float*)d_in[8];
    const float* b_f1    = (const float*)d_in[9];
    const float* wx_b1   = (const float*)d_in[10];
    const float* wh_b1   = (const float*)d_in[11];
    const float* b_b1    = (const float*)d_in[12];
    const float* w_conv1 = (const float*)d_in[13];
    const float* b_conv1 = (const float*)d_in[14];
    const float* w_out   = (const float*)d_in[15];
    const float* b_out   = (const float*)d_in[16];

    float *XG, *Y0, *Y1, *GH, *Z, *RH, *XC, *H1;
    cudaGetSymbolAddress((void**)&XG, g_XG);
    cudaGetSymbolAddress((void**)&Y0, g_Y0);
    cudaGetSymbolAddress((void**)&Y1, g_Y1);
    cudaGetSymbolAddress((void**)&GH, g_GH);
    cudaGetSymbolAddress((void**)&Z,  g_Z);
    cudaGetSymbolAddress((void**)&RH, g_RH);
    cudaGetSymbolAddress((void**)&XC, g_XC);
    cudaGetSymbolAddress((void**)&H1, g_H1);

    const int NIMG = B_ * T_;  // 448

    // Layer 0 input gates: conv(x, wx) + b for both directions -> XG
    conv_launch(x, x, (long)HW_ * 24, 24, 24,
                wx_f0, wx_b0, 192, 0, b_f0, b_b0,
                XG, XG + XG_DIRSTRIDE, (long)HW_ * 192, 192, 0,
                192, NIMG, 2);
    run_layer(XG, Y0, GH, Z, RH, wh_f0, wh_b0);

    // Layer 1 input gates: conv(Y0, wx1) + b1 -> XG (reused)
    conv_launch(Y0, Y0, (long)HW_ * 128, 128, 128,
                wx_f1, wx_b1, 192, 0, b_f1, b_b1,
                XG, XG + XG_DIRSTRIDE, (long)HW_ * 192, 192, 0,
                192, NIMG, 2);
    run_layer(XG, Y1, GH, Z, RH, wh_f1, wh_b1);

    // xr = x0 + bidir1(x0): Y1 += Y0
    long n4 = (long)B_ * T_ * HW_ * 128 / 4;
    add_kernel<<<(unsigned)((n4 + 255) / 256), 256>>>(Y1, Y0, n4);

    // xc = concat(xr, x0) -> XC (256 ch)
    long nPix = (long)NIMG * HW_;
    concat_kernel<<<(unsigned)((nPix * 64 + 255) / 256), 256>>>(Y1, Y0, XC, nPix);

    // conv1: 256 -> 32 + bias
    conv_launch(XC, XC, (long)HW_ * 256, 256, 256,
                w_conv1, w_conv1, 32, 0, b_conv1, b_conv1,
                H1, H1, (long)HW_ * 32, 32, 0,
                32, NIMG, 1);

    // 1x1 conv 32 -> 1 + bias + relu
    int nOut = NIMG * HW_;
    out1x1_kernel<<<(unsigned)((nOut + 255) / 256), 256>>>(H1, w_out, b_out, (float*)d_out, nOut);
}

// round 2
// speedup vs baseline: 2.4041x; 2.4041x over previous
#include <cuda_runtime.h>
#include <math.h>

// ---------------------------------------------------------------------------
// SimpleConvGRU on GB300 — round 2: padded layouts + packed f32x2 FMA.
// All 3x3 convs run on a zero-halo 34x34 layout (no bounds checks, immediate
// address offsets) and pack (cin, cin+1) into fma.rn.f32x2 (2x fp32 rate).
// Weights are pre-transposed per call into [tap][cin/2][cout][2].
// ---------------------------------------------------------------------------

typedef unsigned long long ull;

#define B_ 16
#define T_ 28
#define NIMG_ 448            // B*T
#define PP_ 1156             // 34*34 padded pixels

// ---------------- device scratch (zero-initialized at load) ----------------
__device__ float g_Xpad[(size_t)NIMG_ * PP_ * 24];
__device__ float g_XG[(size_t)2 * NIMG_ * 1024 * 192];   // unpadded gates
__device__ float g_Y0[(size_t)NIMG_ * PP_ * 128];        // padded
__device__ float g_Y1[(size_t)NIMG_ * PP_ * 128];        // padded
__device__ float g_RH[(size_t)32 * PP_ * 64];            // padded
__device__ float g_Z [(size_t)32 * 1024 * 64];           // unpadded
__device__ float g_XC[(size_t)NIMG_ * PP_ * 256];        // padded
__device__ float g_WT[1041408];                          // transposed weights

// transposed-weight offsets (floats)
#define OFF_XF0   0
#define OFF_XB0   41472
#define OFF_ZRF0  82944
#define OFF_ZRB0  156672
#define OFF_HF0   230400
#define OFF_HB0   267264
#define OFF_XF1   304128
#define OFF_XB1   525312
#define OFF_ZRF1  746496
#define OFF_ZRB1  820224
#define OFF_HF1   893952
#define OFF_HB1   930816
#define OFF_C1    967680

// ---------------- packed f32x2 helpers ----------------
__device__ __forceinline__ void fma2(ull& d, ull a, ull b) {
    asm("fma.rn.f32x2 %0, %1, %2, %0;" : "+l"(d) : "l"(a), "l"(b));
}
__device__ __forceinline__ float red2(ull a) {
    float lo, hi;
    asm("mov.b64 {%0,%1}, %2;" : "=f"(lo), "=f"(hi) : "l"(a));
    return lo + hi;
}
__device__ __forceinline__ float sigm(float x) { return 1.0f / (1.0f + expf(-x)); }

// ---------------------------------------------------------------------------
// Core: 3x3 conv on padded input. One warp = 1 output row x 8 px x NC couts
// (lane -> cout, partner cout = +32). Accumulates (even,odd) cin partials in
// f32x2. CINH = Cin/2, CSTRIDE = input pixel stride, WCO = cout dim of wt.
// wt layout: [9][CINH][WCO][2] floats.
// ---------------------------------------------------------------------------
template<int CINH, int CSTRIDE, int WCO, int NC>
__device__ __forceinline__ void conv_core(
    const float* __restrict__ in, const float* __restrict__ wt,
    int coutIdx, int y, int x0, ull acc[NC][8])
{
#pragma unroll
    for (int nc = 0; nc < NC; nc++)
#pragma unroll
        for (int p = 0; p < 8; p++) acc[nc][p] = 0ull;

    const float* inP = in + ((y - 1) * 34 + (x0 - 1)) * CSTRIDE;
    const float* wP  = wt + coutIdx * 2;

#pragma unroll 1
    for (int cp = 0; cp < CINH; cp++) {
#pragma unroll
        for (int ky = 0; ky < 3; ky++) {
            ull v[10];
#pragma unroll
            for (int q = 0; q < 10; q++)
                v[q] = *(const ull*)(inP + (ky * 34 + q) * CSTRIDE);
#pragma unroll
            for (int kx = 0; kx < 3; kx++) {
#pragma unroll
                for (int nc = 0; nc < NC; nc++) {
                    ull w = *(const ull*)(wP + ((ky * 3 + kx) * CINH * WCO + nc * 32) * 2);
#pragma unroll
                    for (int p = 0; p < 8; p++)
                        fma2(acc[nc][p], v[p + kx], w);
                }
            }
        }
        inP += 2;
        wP  += WCO * 2;
    }
}

// ---------------------------------------------------------------------------
// Input-gate conv: (x or Y0, both dirs) -> XG (+bias). Cout=192 in 3 groups.
// grid = (4, 4, 2*448*3), block 256.
// ---------------------------------------------------------------------------
template<int CINH, int CSTRIDE>
__global__ __launch_bounds__(256, 2) void conv_gates_k(
    const float* __restrict__ in, long imgStride,
    const float* __restrict__ wtF, const float* __restrict__ wtB,
    const float* __restrict__ bF, const float* __restrict__ bB,
    float* __restrict__ XG)
{
    int z = blockIdx.z;
    int dir = z / (NIMG_ * 3);
    int rem = z - dir * (NIMG_ * 3);
    int img = rem / 3, cg = rem - (rem / 3) * 3;
    int lane = threadIdx.x & 31, warp = threadIdx.x >> 5;
    int y  = blockIdx.y * 8 + warp + 1;
    int x0 = blockIdx.x * 8 + 1;
    int co = cg * 64 + lane;

    ull acc[2][8];
    conv_core<CINH, CSTRIDE, 192, 2>(in + (long)img * imgStride,
                                     dir ? wtB : wtF, co, y, x0, acc);

    const float* bias = dir ? bB : bF;
    float* xg = XG + (((long)dir * NIMG_ + img) * 1024 + (long)(y - 1) * 32 + (x0 - 1)) * 192;
#pragma unroll
    for (int nc = 0; nc < 2; nc++) {
        int c = co + nc * 32;
        float bv = bias[c];
#pragma unroll
        for (int p = 0; p < 8; p++) xg[p * 192 + c] = red2(acc[nc][p]) + bv;
    }
}

// ---------------------------------------------------------------------------
// Recurrent gate conv (h_prev -> z/r) fused with sigmoid + RH = r*h.
// grid = (4, 4, 64): z = dir*32 + b*2 + cg. cg0 = z gates, cg1 = r gates.
// ---------------------------------------------------------------------------
__global__ __launch_bounds__(256, 2) void conv_gh_zrh_k(
    const float* __restrict__ Y,
    const float* __restrict__ wtF, const float* __restrict__ wtB,
    const float* __restrict__ XG, float* __restrict__ Z, float* __restrict__ RH,
    int tf, int tb)
{
    int z = blockIdx.z;
    int dir = z >> 5, b = (z >> 1) & 15, cg = z & 1;
    int lane = threadIdx.x & 31, warp = threadIdx.x >> 5;
    int y  = blockIdx.y * 8 + warp + 1;
    int x0 = blockIdx.x * 8 + 1;
    int t = dir ? tb : tf;
    int tprev = dir ? tb + 1 : tf - 1;

    const float* hbase = Y + (long)(b * T_ + tprev) * PP_ * 128 + (dir ? 64 : 0);
    ull acc[2][8];
    conv_core<32, 128, 128, 2>(hbase, dir ? wtB : wtF, cg * 64 + lane, y, x0, acc);

    const float* xg = XG + (((long)dir * NIMG_ + b * T_ + t) * 1024 + (long)(y - 1) * 32 + (x0 - 1)) * 192;
    if (cg == 0) {
        float* zp = Z + ((long)(dir * 16 + b) * 1024 + (long)(y - 1) * 32 + (x0 - 1)) * 64;
#pragma unroll
        for (int nc = 0; nc < 2; nc++) {
            int c = lane + nc * 32;
#pragma unroll
            for (int p = 0; p < 8; p++)
                zp[p * 64 + c] = sigm(xg[p * 192 + c] + red2(acc[nc][p]));
        }
    } else {
        float* rh = RH + ((long)(dir * 16 + b) * PP_ + (long)y * 34 + x0) * 64;
#pragma unroll
        for (int nc = 0; nc < 2; nc++) {
            int c = lane + nc * 32;
#pragma unroll
            for (int p = 0; p < 8; p++) {
                float r = sigm(xg[p * 192 + 64 + c] + red2(acc[nc][p]));
                float h = hbase[((long)y * 34 + x0 + p) * 128 + c];
                rh[p * 64 + c] = r * h;
            }
        }
    }
}

// ---------------------------------------------------------------------------
// Candidate conv (RH -> hh) fused with tanh + GRU blend, writes Y[t].
// grid = (4, 4, 32): z = dir*16 + b.
// ---------------------------------------------------------------------------
__global__ __launch_bounds__(256, 2) void conv_blend_k(
    const float* __restrict__ RH,
    const float* __restrict__ wtF, const float* __restrict__ wtB,
    const float* __restrict__ XG, const float* __restrict__ Z,
    float* __restrict__ Y, int tf, int tb)
{
    int z = blockIdx.z;
    int dir = z >> 4, b = z & 15;
    int lane = threadIdx.x & 31, warp = threadIdx.x >> 5;
    int y  = blockIdx.y * 8 + warp + 1;
    int x0 = blockIdx.x * 8 + 1;
    int t = dir ? tb : tf;
    int tprev = dir ? tb + 1 : tf - 1;

    const float* in = RH + (long)(dir * 16 + b) * PP_ * 64;
    ull acc[2][8];
    conv_core<32, 64, 64, 2>(in, dir ? wtB : wtF, lane, y, x0, acc);

    const float* xg = XG + (((long)dir * NIMG_ + b * T_ + t) * 1024 + (long)(y - 1) * 32 + (x0 - 1)) * 192;
    const float* zp = Z + ((long)(dir * 16 + b) * 1024 + (long)(y - 1) * 32 + (x0 - 1)) * 64;
    const float* hprev = Y + (long)(b * T_ + tprev) * PP_ * 128 + (dir ? 64 : 0);
    float* yout = Y + (long)(b * T_ + t) * PP_ * 128 + (dir ? 64 : 0);
#pragma unroll
    for (int nc = 0; nc < 2; nc++) {
        int c = lane + nc * 32;
#pragma unroll
        for (int p = 0; p < 8; p++) {
            float cand = tanhf(xg[p * 192 + 128 + c] + red2(acc[nc][p]));
            float zv = zp[p * 64 + c];
            float hv = hprev[((long)y * 34 + x0 + p) * 128 + c];
            yout[((long)y * 34 + x0 + p) * 128 + c] = zv * hv + (1.0f - zv) * cand;
        }
    }
}

// ---------------------------------------------------------------------------
// conv1 (256->32) fused with the 1x1 head + ReLU (warp-shuffle reduce).
// grid = (4, 4, 448). NC=1 (Cout=32 = one lane group).
// ---------------------------------------------------------------------------
__global__ __launch_bounds__(256, 2) void conv1_out_k(
    const float* __restrict__ XC, const float* __restrict__ wt,
    const float* __restrict__ bc, const float* __restrict__ wo,
    const float* __restrict__ bo, float* __restrict__ out)
{
    int img = blockIdx.z;
    int lane = threadIdx.x & 31, warp = threadIdx.x >> 5;
    int y  = blockIdx.y * 8 + warp + 1;
    int x0 = blockIdx.x * 8 + 1;

    ull acc[1][8];
    conv_core<128, 256, 32, 1>(XC + (long)img * PP_ * 256, wt, lane, y, x0, acc);

    float bv = bc[lane], wv = wo[lane], bov = bo[0];
    float* o = out + (long)img * 1024 + (long)(y - 1) * 32 + (x0 - 1);
#pragma unroll
    for (int p = 0; p < 8; p++) {
        float s = (red2(acc[0][p]) + bv) * wv;
        s += __shfl_xor_sync(0xffffffffu, s, 16);
        s += __shfl_xor_sync(0xffffffffu, s, 8);
        s += __shfl_xor_sync(0xffffffffu, s, 4);
        s += __shfl_xor_sync(0xffffffffu, s, 2);
        s += __shfl_xor_sync(0xffffffffu, s, 1);
        if (lane == 0) o[p] = fmaxf(s + bov, 0.0f);
    }
}

// ---------------------------------------------------------------------------
// t=0 step (h_prev = 0): y = (1-sig(xg_z)) * tanh(xg_h), elementwise.
// ---------------------------------------------------------------------------
__global__ __launch_bounds__(256) void zrh0_k(const float* __restrict__ XG,
                                              float* __restrict__ Y)
{
    int i = blockIdx.x * 256 + threadIdx.x;   // 2*16*1024*64
    int c = i & 63;
    int t1 = i >> 6;
    int pix = t1 & 1023;
    int t2 = t1 >> 10;
    int b = t2 & 15, dir = t2 >> 4;
    int t = dir ? T_ - 1 : 0;
    const float* xg = XG + (((long)dir * NIMG_ + b * T_ + t) * 1024 + pix) * 192;
    float zv = sigm(xg[c]);
    float yv = (1.0f - zv) * tanhf(xg[128 + c]);
    int yy = pix >> 5, xx = pix & 31;
    Y[((long)(b * T_ + t) * PP_ + (long)(yy + 1) * 34 + xx + 1) * 128 + dir * 64 + c] = yv;
}

// ---------------------------------------------------------------------------
// Small utility kernels
// ---------------------------------------------------------------------------
__global__ __launch_bounds__(256) void transpose_w_k(
    const float* __restrict__ src, float* __restrict__ dst,
    int CIN, int COsrc, int o0, int WCO)
{
    int n = 9 * (CIN / 2) * WCO;
    int i = blockIdx.x * 256 + threadIdx.x;
    if (i >= n) return;
    int co = i % WCO;
    int r = i / WCO;
    int cp = r % (CIN / 2);
    int tap = r / (CIN / 2);
    dst[(long)i * 2 + 0] = src[((long)tap * CIN + 2 * cp) * COsrc + o0 + co];
    dst[(long)i * 2 + 1] = src[((long)tap * CIN + 2 * cp + 1) * COsrc + o0 + co];
}

__global__ __launch_bounds__(256) void pad_x_k(const float* __restrict__ x,
                                               float* __restrict__ xp)
{
    long i = (long)blockIdx.x * 256 + threadIdx.x;   // 448*1156*24
    if (i >= (long)NIMG_ * PP_ * 24) return;
    int c = (int)(i % 24);
    long r = i / 24;
    int pix = (int)(r % PP_);
    long img = r / PP_;
    int y = pix / 34, xx = pix % 34;
    float v = 0.0f;
    if (y >= 1 && y <= 32 && xx >= 1 && xx <= 32)
        v = x[(((long)img * 32 + y - 1) * 32 + xx - 1) * 24 + c];
    xp[i] = v;
}

__global__ __launch_bounds__(256) void halo_zero_k(float* __restrict__ p, int nImg, int C)
{
    long i = (long)blockIdx.x * 256 + threadIdx.x;
    long tot = (long)nImg * 132 * C;
    if (i >= tot) return;
    int c = (int)(i % C);
    long r = i / C;
    int hidx = (int)(r % 132);
    long img = r / 132;
    int y, x;
    if (hidx < 34)       { y = 0;  x = hidx; }
    else if (hidx < 68)  { y = 33; x = hidx - 34; }
    else if (hidx < 100) { y = hidx - 68 + 1;  x = 0; }
    else                 { y = hidx - 100 + 1; x = 33; }
    p[((long)img * PP_ + (long)y * 34 + x) * C + c] = 0.0f;
}

__global__ __launch_bounds__(256) void addconcat_k(
    const float* __restrict__ Y0, const float* __restrict__ Y1,
    float* __restrict__ XC)
{
    long i = (long)blockIdx.x * 256 + threadIdx.x;   // 448*1024*64 float4 units
    if (i >= (long)NIMG_ * 1024 * 64) return;
    int cq = (int)(i & 63);
    long r = i >> 6;
    int pix = (int)(r & 1023);
    long img = r >> 10;
    int c = cq * 4;
    int y = pix >> 5, xx = pix & 31;
    long pp = (long)(y + 1) * 34 + xx + 1;
    float4 v;
    if (c < 128) {
        float4 a = *(const float4*)(Y0 + (img * PP_ + pp) * 128 + c);
        float4 bq = *(const float4*)(Y1 + (img * PP_ + pp) * 128 + c);
        v = make_float4(a.x + bq.x, a.y + bq.y, a.z + bq.z, a.w + bq.w);
    } else {
        v = *(const float4*)(Y0 + (img * PP_ + pp) * 128 + c - 128);
    }
    *(float4*)(XC + (img * PP_ + pp) * 256 + c) = v;
}

// ---------------------------------------------------------------------------
// Host
// ---------------------------------------------------------------------------
static void trans(const float* src, float* WT, long dstOff, int CIN, int COsrc,
                  int o0, int WCO)
{
    int n = 9 * (CIN / 2) * WCO;
    transpose_w_k<<<(n + 255) / 256, 256>>>(src, WT + dstOff, CIN, COsrc, o0, WCO);
}

static void run_layer(const float* XG_, float* Y, float* Z_, float* RH_,
                      const float* WT, long zrF, long zrB, long hF, long hB)
{
    zrh0_k<<<8192, 256>>>(XG_, Y);
    for (int i = 1; i < T_; i++) {
        conv_gh_zrh_k<<<dim3(4, 4, 64), 256>>>(Y, WT + zrF, WT + zrB, XG_, Z_, RH_,
                                               i, T_ - 1 - i);
        conv_blend_k<<<dim3(4, 4, 32), 256>>>(RH_, WT + hF, WT + hB, XG_, Z_, Y,
                                              i, T_ - 1 - i);
    }
}

extern "C" void kernel_launch(void* const* d_in, const int* in_sizes, int n_in,
                              void* d_out, int out_size)
{
    (void)in_sizes; (void)n_in; (void)out_size;
    const float* x       = (const float*)d_in[0];
    const float* wx_f0   = (const float*)d_in[1];
    const float* wh_f0   = (const float*)d_in[2];
    const float* b_f0    = (const float*)d_in[3];
    const float* wx_b0   = (const float*)d_in[4];
    const float* wh_b0   = (const float*)d_in[5];
    const float* b_b0    = (const float*)d_in[6];
    const float* wx_f1   = (const float*)d_in[7];
    const float* wh_f1   = (const float*)d_in[8];
    const float* b_f1    = (const float*)d_in[9];
    const float* wx_b1   = (const float*)d_in[10];
    const float* wh_b1   = (const float*)d_in[11];
    const float* b_b1    = (const float*)d_in[12];
    const float* w_conv1 = (const float*)d_in[13];
    const float* b_conv1 = (const float*)d_in[14];
    const float* w_out   = (const float*)d_in[15];
    const float* b_out   = (const float*)d_in[16];

    float *Xpad, *XG, *Y0, *Y1, *RH, *Z, *XC, *WT;
    cudaGetSymbolAddress((void**)&Xpad, g_Xpad);
    cudaGetSymbolAddress((void**)&XG, g_XG);
    cudaGetSymbolAddress((void**)&Y0, g_Y0);
    cudaGetSymbolAddress((void**)&Y1, g_Y1);
    cudaGetSymbolAddress((void**)&RH, g_RH);
    cudaGetSymbolAddress((void**)&Z,  g_Z);
    cudaGetSymbolAddress((void**)&XC, g_XC);
    cudaGetSymbolAddress((void**)&WT, g_WT);

    // --- weight transposes ---
    trans(wx_f0, WT, OFF_XF0, 24, 192, 0, 192);
    trans(wx_b0, WT, OFF_XB0, 24, 192, 0, 192);
    trans(wh_f0, WT, OFF_ZRF0, 64, 192, 0, 128);
    trans(wh_b0, WT, OFF_ZRB0, 64, 192, 0, 128);
    trans(wh_f0, WT, OFF_HF0, 64, 192, 128, 64);
    trans(wh_b0, WT, OFF_HB0, 64, 192, 128, 64);
    trans(wx_f1, WT, OFF_XF1, 128, 192, 0, 192);
    trans(wx_b1, WT, OFF_XB1, 128, 192, 0, 192);
    trans(wh_f1, WT, OFF_ZRF1, 64, 192, 0, 128);
    trans(wh_b1, WT, OFF_ZRB1, 64, 192, 0, 128);
    trans(wh_f1, WT, OFF_HF1, 64, 192, 128, 64);
    trans(wh_b1, WT, OFF_HB1, 64, 192, 128, 64);
    trans(w_conv1, WT, OFF_C1, 256, 32, 0, 32);

    // --- input padding + halo zeroing ---
    {
        long n = (long)NIMG_ * PP_ * 24;
        pad_x_k<<<(unsigned)((n + 255) / 256), 256>>>(x, Xpad);
    }
    halo_zero_k<<<(NIMG_ * 132 * 128 + 255) / 256, 256>>>(Y0, NIMG_, 128);
    halo_zero_k<<<(NIMG_ * 132 * 128 + 255) / 256, 256>>>(Y1, NIMG_, 128);
    halo_zero_k<<<(32 * 132 * 64 + 255) / 256, 256>>>(RH, 32, 64);
    halo_zero_k<<<(NIMG_ * 132 * 256 + 255) / 256, 256>>>(XC, NIMG_, 256);

    // --- layer 0 ---
    conv_gates_k<12, 24><<<dim3(4, 4, 2 * NIMG_ * 3), 256>>>(
        Xpad, (long)PP_ * 24, WT + OFF_XF0, WT + OFF_XB0, b_f0, b_b0, XG);
    run_layer(XG, Y0, Z, RH, WT, OFF_ZRF0, OFF_ZRB0, OFF_HF0, OFF_HB0);

    // --- layer 1 ---
    conv_gates_k<64, 128><<<dim3(4, 4, 2 * NIMG_ * 3), 256>>>(
        Y0, (long)PP_ * 128, WT + OFF_XF1, WT + OFF_XB1, b_f1, b_b1, XG);
    run_layer(XG, Y1, Z, RH, WT, OFF_ZRF1, OFF_ZRB1, OFF_HF1, OFF_HB1);

    // --- xr = Y0+Y1, xc = [xr, Y0] ---
    {
        long n = (long)NIMG_ * 1024 * 64;
        addconcat_k<<<(unsigned)((n + 255) / 256), 256>>>(Y0, Y1, XC);
    }

    // --- conv1 + 1x1 + relu ---
    conv1_out_k<<<dim3(4, 4, NIMG_), 256>>>(XC, WT + OFF_C1, b_conv1, w_out, b_out,
                                            (float*)d_out);
}

// round 3
// speedup vs baseline: 2.4046x; 1.0002x over previous
#include <cuda_runtime.h>
#include <math.h>

// ---------------------------------------------------------------------------
// SimpleConvGRU on GB300 — round 2: padded layouts + packed f32x2 FMA.
// All 3x3 convs run on a zero-halo 34x34 layout (no bounds checks, immediate
// address offsets) and pack (cin, cin+1) into fma.rn.f32x2 (2x fp32 rate).
// Weights are pre-transposed per call into [tap][cin/2][cout][2].
// ---------------------------------------------------------------------------

typedef unsigned long long ull;

#define B_ 16
#define T_ 28
#define NIMG_ 448            // B*T
#define PP_ 1156             // 34*34 padded pixels

// ---------------- device scratch (zero-initialized at load) ----------------
__device__ float g_Xpad[(size_t)NIMG_ * PP_ * 24];
__device__ float g_XG[(size_t)2 * NIMG_ * 1024 * 192];   // unpadded gates
__device__ float g_Y0[(size_t)NIMG_ * PP_ * 128];        // padded
__device__ float g_Y1[(size_t)NIMG_ * PP_ * 128];        // padded
__device__ float g_RH[(size_t)32 * PP_ * 64];            // padded
__device__ float g_Z [(size_t)32 * 1024 * 64];           // unpadded
__device__ float g_XC[(size_t)NIMG_ * PP_ * 256];        // padded
__device__ float g_WT[1041408];                          // transposed weights

// transposed-weight offsets (floats)
#define OFF_XF0   0
#define OFF_XB0   41472
#define OFF_ZRF0  82944
#define OFF_ZRB0  156672
#define OFF_HF0   230400
#define OFF_HB0   267264
#define OFF_XF1   304128
#define OFF_XB1   525312
#define OFF_ZRF1  746496
#define OFF_ZRB1  820224
#define OFF_HF1   893952
#define OFF_HB1   930816
#define OFF_C1    967680

// ---------------- packed f32x2 helpers ----------------
__device__ __forceinline__ void fma2(ull& d, ull a, ull b) {
    asm("fma.rn.f32x2 %0, %1, %2, %0;" : "+l"(d) : "l"(a), "l"(b));
}
__device__ __forceinline__ float red2(ull a) {
    float lo, hi;
    asm("mov.b64 {%0,%1}, %2;" : "=f"(lo), "=f"(hi) : "l"(a));
    return lo + hi;
}
__device__ __forceinline__ float sigm(float x) { return 1.0f / (1.0f + expf(-x)); }

// ---------------------------------------------------------------------------
// Core: 3x3 conv on padded input. One warp = 1 output row x 8 px x NC couts
// (lane -> cout, partner cout = +32). Accumulates (even,odd) cin partials in
// f32x2. CINH = Cin/2, CSTRIDE = input pixel stride, WCO = cout dim of wt.
// wt layout: [9][CINH][WCO][2] floats.
// ---------------------------------------------------------------------------
template<int CINH, int CSTRIDE, int WCO, int NC>
__device__ __forceinline__ void conv_core(
    const float* __restrict__ in, const float* __restrict__ wt,
    int coutIdx, int y, int x0, ull acc[NC][8])
{
#pragma unroll
    for (int nc = 0; nc < NC; nc++)
#pragma unroll
        for (int p = 0; p < 8; p++) acc[nc][p] = 0ull;

    const float* inP = in + ((y - 1) * 34 + (x0 - 1)) * CSTRIDE;
    const float* wP  = wt + coutIdx * 2;

#pragma unroll 1
    for (int cp = 0; cp < CINH; cp++) {
#pragma unroll
        for (int ky = 0; ky < 3; ky++) {
            ull v[10];
#pragma unroll
            for (int q = 0; q < 10; q++)
                v[q] = *(const ull*)(inP + (ky * 34 + q) * CSTRIDE);
#pragma unroll
            for (int kx = 0; kx < 3; kx++) {
#pragma unroll
                for (int nc = 0; nc < NC; nc++) {
                    ull w = *(const ull*)(wP + ((ky * 3 + kx) * CINH * WCO + nc * 32) * 2);
#pragma unroll
                    for (int p = 0; p < 8; p++)
                        fma2(acc[nc][p], v[p + kx], w);
                }
            }
        }
        inP += 2;
        wP  += WCO * 2;
    }
}

// ---------------------------------------------------------------------------
// Input-gate conv: (x or Y0, both dirs) -> XG (+bias). Cout=192 in 3 groups.
// grid = (4, 4, 2*448*3), block 256.
// ---------------------------------------------------------------------------
template<int CINH, int CSTRIDE>
__global__ __launch_bounds__(256, 2) void conv_gates_k(
    const float* __restrict__ in, long imgStride,
    const float* __restrict__ wtF, const float* __restrict__ wtB,
    const float* __restrict__ bF, const float* __restrict__ bB,
    float* __restrict__ XG)
{
    int z = blockIdx.z;
    int dir = z / (NIMG_ * 3);
    int rem = z - dir * (NIMG_ * 3);
    int img = rem / 3, cg = rem - (rem / 3) * 3;
    int lane = threadIdx.x & 31, warp = threadIdx.x >> 5;
    int y  = blockIdx.y * 8 + warp + 1;
    int x0 = blockIdx.x * 8 + 1;
    int co = cg * 64 + lane;

    ull acc[2][8];
    conv_core<CINH, CSTRIDE, 192, 2>(in + (long)img * imgStride,
                                     dir ? wtB : wtF, co, y, x0, acc);

    const float* bias = dir ? bB : bF;
    float* xg = XG + (((long)dir * NIMG_ + img) * 1024 + (long)(y - 1) * 32 + (x0 - 1)) * 192;
#pragma unroll
    for (int nc = 0; nc < 2; nc++) {
        int c = co + nc * 32;
        float bv = bias[c];
#pragma unroll
        for (int p = 0; p < 8; p++) xg[p * 192 + c] = red2(acc[nc][p]) + bv;
    }
}

// ---------------------------------------------------------------------------
// Recurrent gate conv (h_prev -> z/r) fused with sigmoid + RH = r*h.
// grid = (4, 4, 64): z = dir*32 + b*2 + cg. cg0 = z gates, cg1 = r gates.
// ---------------------------------------------------------------------------
__global__ __launch_bounds__(256, 2) void conv_gh_zrh_k(
    const float* __restrict__ Y,
    const float* __restrict__ wtF, const float* __restrict__ wtB,
    const float* __restrict__ XG, float* __restrict__ Z, float* __restrict__ RH,
    int tf, int tb)
{
    int z = blockIdx.z;
    int dir = z >> 5, b = (z >> 1) & 15, cg = z & 1;
    int lane = threadIdx.x & 31, warp = threadIdx.x >> 5;
    int y  = blockIdx.y * 8 + warp + 1;
    int x0 = blockIdx.x * 8 + 1;
    int t = dir ? tb : tf;
    int tprev = dir ? tb + 1 : tf - 1;

    const float* hbase = Y + (long)(b * T_ + tprev) * PP_ * 128 + (dir ? 64 : 0);
    ull acc[2][8];
    conv_core<32, 128, 128, 2>(hbase, dir ? wtB : wtF, cg * 64 + lane, y, x0, acc);

    const float* xg = XG + (((long)dir * NIMG_ + b * T_ + t) * 1024 + (long)(y - 1) * 32 + (x0 - 1)) * 192;
    if (cg == 0) {
        float* zp = Z + ((long)(dir * 16 + b) * 1024 + (long)(y - 1) * 32 + (x0 - 1)) * 64;
#pragma unroll
        for (int nc = 0; nc < 2; nc++) {
            int c = lane + nc * 32;
#pragma unroll
            for (int p = 0; p < 8; p++)
                zp[p * 64 + c] = sigm(xg[p * 192 + c] + red2(acc[nc][p]));
        }
    } else {
        float* rh = RH + ((long)(dir * 16 + b) * PP_ + (long)y * 34 + x0) * 64;
#pragma unroll
        for (int nc = 0; nc < 2; nc++) {
            int c = lane + nc * 32;
#pragma unroll
            for (int p = 0; p < 8; p++) {
                float r = sigm(xg[p * 192 + 64 + c] + red2(acc[nc][p]));
                float h = hbase[((long)y * 34 + x0 + p) * 128 + c];
                rh[p * 64 + c] = r * h;
            }
        }
    }
}

// ---------------------------------------------------------------------------
// Candidate conv (RH -> hh) fused with tanh + GRU blend, writes Y[t].
// grid = (4, 4, 32): z = dir*16 + b.
// ---------------------------------------------------------------------------
__global__ __launch_bounds__(256, 2) void conv_blend_k(
    const float* __restrict__ RH,
    const float* __restrict__ wtF, const float* __restrict__ wtB,
    const float* __restrict__ XG, const float* __restrict__ Z,
    float* __restrict__ Y, int tf, int tb)
{
    int z = blockIdx.z;
    int dir = z >> 4, b = z & 15;
    int lane = threadIdx.x & 31, warp = threadIdx.x >> 5;
    int y  = blockIdx.y * 8 + warp + 1;
    int x0 = blockIdx.x * 8 + 1;
    int t = dir ? tb : tf;
    int tprev = dir ? tb + 1 : tf - 1;

    const float* in = RH + (long)(dir * 16 + b) * PP_ * 64;
    ull acc[2][8];
    conv_core<32, 64, 64, 2>(in, dir ? wtB : wtF, lane, y, x0, acc);

    const float* xg = XG + (((long)dir * NIMG_ + b * T_ + t) * 1024 + (long)(y - 1) * 32 + (x0 - 1)) * 192;
    const float* zp = Z + ((long)(dir * 16 + b) * 1024 + (long)(y - 1) * 32 + (x0 - 1)) * 64;
    const float* hprev = Y + (long)(b * T_ + tprev) * PP_ * 128 + (dir ? 64 : 0);
    float* yout = Y + (long)(b * T_ + t) * PP_ * 128 + (dir ? 64 : 0);
#pragma unroll
    for (int nc = 0; nc < 2; nc++) {
        int c = lane + nc * 32;
#pragma unroll
        for (int p = 0; p < 8; p++) {
            float cand = tanhf(xg[p * 192 + 128 + c] + red2(acc[nc][p]));
            float zv = zp[p * 64 + c];
            float hv = hprev[((long)y * 34 + x0 + p) * 128 + c];
            yout[((long)y * 34 + x0 + p) * 128 + c] = zv * hv + (1.0f - zv) * cand;
        }
    }
}

// ---------------------------------------------------------------------------
// conv1 (256->32) fused with the 1x1 head + ReLU (warp-shuffle reduce).
// grid = (4, 4, 448). NC=1 (Cout=32 = one lane group).
// ---------------------------------------------------------------------------
__global__ __launch_bounds__(256, 2) void conv1_out_k(
    const float* __restrict__ XC, const float* __restrict__ wt,
    const float* __restrict__ bc, const float* __restrict__ wo,
    const float* __restrict__ bo, float* __restrict__ out)
{
    int img = blockIdx.z;
    int lane = threadIdx.x & 31, warp = threadIdx.x >> 5;
    int y  = blockIdx.y * 8 + warp + 1;
    int x0 = blockIdx.x * 8 + 1;

    ull acc[1][8];
    conv_core<128, 256, 32, 1>(XC + (long)img * PP_ * 256, wt, lane, y, x0, acc);

    float bv = bc[lane], wv = wo[lane], bov = bo[0];
    float* o = out + (long)img * 1024 + (long)(y - 1) * 32 + (x0 - 1);
#pragma unroll
    for (int p = 0; p < 8; p++) {
        float s = (red2(acc[0][p]) + bv) * wv;
        s += __shfl_xor_sync(0xffffffffu, s, 16);
        s += __shfl_xor_sync(0xffffffffu, s, 8);
        s += __shfl_xor_sync(0xffffffffu, s, 4);
        s += __shfl_xor_sync(0xffffffffu, s, 2);
        s += __shfl_xor_sync(0xffffffffu, s, 1);
        if (lane == 0) o[p] = fmaxf(s + bov, 0.0f);
    }
}

// ---------------------------------------------------------------------------
// t=0 step (h_prev = 0): y = (1-sig(xg_z)) * tanh(xg_h), elementwise.
// ---------------------------------------------------------------------------
__global__ __launch_bounds__(256) void zrh0_k(const float* __restrict__ XG,
                                              float* __restrict__ Y)
{
    int i = blockIdx.x * 256 + threadIdx.x;   // 2*16*1024*64
    int c = i & 63;
    int t1 = i >> 6;
    int pix = t1 & 1023;
    int t2 = t1 >> 10;
    int b = t2 & 15, dir = t2 >> 4;
    int t = dir ? T_ - 1 : 0;
    const float* xg = XG + (((long)dir * NIMG_ + b * T_ + t) * 1024 + pix) * 192;
    float zv = sigm(xg[c]);
    float yv = (1.0f - zv) * tanhf(xg[128 + c]);
    int yy = pix >> 5, xx = pix & 31;
    Y[((long)(b * T_ + t) * PP_ + (long)(yy + 1) * 34 + xx + 1) * 128 + dir * 64 + c] = yv;
}

// ---------------------------------------------------------------------------
// Small utility kernels
// ---------------------------------------------------------------------------
__global__ __launch_bounds__(256) void transpose_w_k(
    const float* __restrict__ src, float* __restrict__ dst,
    int CIN, int COsrc, int o0, int WCO)
{
    int n = 9 * (CIN / 2) * WCO;
    int i = blockIdx.x * 256 + threadIdx.x;
    if (i >= n) return;
    int co = i % WCO;
    int r = i / WCO;
    int cp = r % (CIN / 2);
    int tap = r / (CIN / 2);
    dst[(long)i * 2 + 0] = src[((long)tap * CIN + 2 * cp) * COsrc + o0 + co];
    dst[(long)i * 2 + 1] = src[((long)tap * CIN + 2 * cp + 1) * COsrc + o0 + co];
}

__global__ __launch_bounds__(256) void pad_x_k(const float* __restrict__ x,
                                               float* __restrict__ xp)
{
    long i = (long)blockIdx.x * 256 + threadIdx.x;   // 448*1156*24
    if (i >= (long)NIMG_ * PP_ * 24) return;
    int c = (int)(i % 24);
    long r = i / 24;
    int pix = (int)(r % PP_);
    long img = r / PP_;
    int y = pix / 34, xx = pix % 34;
    float v = 0.0f;
    if (y >= 1 && y <= 32 && xx >= 1 && xx <= 32)
        v = x[(((long)img * 32 + y - 1) * 32 + xx - 1) * 24 + c];
    xp[i] = v;
}

__global__ __launch_bounds__(256) void halo_zero_k(float* __restrict__ p, int nImg, int C)
{
    long i = (long)blockIdx.x * 256 + threadIdx.x;
    long tot = (long)nImg * 132 * C;
    if (i >= tot) return;
    int c = (int)(i % C);
    long r = i / C;
    int hidx = (int)(r % 132);
    long img = r / 132;
    int y, x;
    if (hidx < 34)       { y = 0;  x = hidx; }
    else if (hidx < 68)  { y = 33; x = hidx - 34; }
    else if (hidx < 100) { y = hidx - 68 + 1;  x = 0; }
    else                 { y = hidx - 100 + 1; x = 33; }
    p[((long)img * PP_ + (long)y * 34 + x) * C + c] = 0.0f;
}

__global__ __launch_bounds__(256) void addconcat_k(
    const float* __restrict__ Y0, const float* __restrict__ Y1,
    float* __restrict__ XC)
{
    long i = (long)blockIdx.x * 256 + threadIdx.x;   // 448*1024*64 float4 units
    if (i >= (long)NIMG_ * 1024 * 64) return;
    int cq = (int)(i & 63);
    long r = i >> 6;
    int pix = (int)(r & 1023);
    long img = r >> 10;
    int c = cq * 4;
    int y = pix >> 5, xx = pix & 31;
    long pp = (long)(y + 1) * 34 + xx + 1;
    float4 v;
    if (c < 128) {
        float4 a = *(const float4*)(Y0 + (img * PP_ + pp) * 128 + c);
        float4 bq = *(const float4*)(Y1 + (img * PP_ + pp) * 128 + c);
        v = make_float4(a.x + bq.x, a.y + bq.y, a.z + bq.z, a.w + bq.w);
    } else {
        v = *(const float4*)(Y0 + (img * PP_ + pp) * 128 + c - 128);
    }
    *(float4*)(XC + (img * PP_ + pp) * 256 + c) = v;
}

// ---------------------------------------------------------------------------
// Host
// ---------------------------------------------------------------------------
static void trans(const float* src, float* WT, long dstOff, int CIN, int COsrc,
                  int o0, int WCO)
{
    int n = 9 * (CIN / 2) * WCO;
    transpose_w_k<<<(n + 255) / 256, 256>>>(src, WT + dstOff, CIN, COsrc, o0, WCO);
}

static void run_layer(const float* XG_, float* Y, float* Z_, float* RH_,
                      const float* WT, long zrF, long zrB, long hF, long hB)
{
    zrh0_k<<<8192, 256>>>(XG_, Y);
    for (int i = 1; i < T_; i++) {
        conv_gh_zrh_k<<<dim3(4, 4, 64), 256>>>(Y, WT + zrF, WT + zrB, XG_, Z_, RH_,
                                               i, T_ - 1 - i);
        conv_blend_k<<<dim3(4, 4, 32), 256>>>(RH_, WT + hF, WT + hB, XG_, Z_, Y,
                                              i, T_ - 1 - i);
    }
}

extern "C" void kernel_launch(void* const* d_in, const int* in_sizes, int n_in,
                              void* d_out, int out_size)
{
    (void)in_sizes; (void)n_in; (void)out_size;
    const float* x       = (const float*)d_in[0];
    const float* wx_f0   = (const float*)d_in[1];
    const float* wh_f0   = (const float*)d_in[2];
    const float* b_f0    = (const float*)d_in[3];
    const float* wx_b0   = (const float*)d_in[4];
    const float* wh_b0   = (const float*)d_in[5];
    const float* b_b0    = (const float*)d_in[6];
    const float* wx_f1   = (const float*)d_in[7];
    const float* wh_f1   = (const float*)d_in[8];
    const float* b_f1    = (const float*)d_in[9];
    const float* wx_b1   = (const float*)d_in[10];
    const float* wh_b1   = (const float*)d_in[11];
    const float* b_b1    = (const float*)d_in[12];
    const float* w_conv1 = (const float*)d_in[13];
    const float* b_conv1 = (const float*)d_in[14];
    const float* w_out   = (const float*)d_in[15];
    const float* b_out   = (const float*)d_in[16];

    float *Xpad, *XG, *Y0, *Y1, *RH, *Z, *XC, *WT;
    cudaGetSymbolAddress((void**)&Xpad, g_Xpad);
    cudaGetSymbolAddress((void**)&XG, g_XG);
    cudaGetSymbolAddress((void**)&Y0, g_Y0);
    cudaGetSymbolAddress((void**)&Y1, g_Y1);
    cudaGetSymbolAddress((void**)&RH, g_RH);
    cudaGetSymbolAddress((void**)&Z,  g_Z);
    cudaGetSymbolAddress((void**)&XC, g_XC);
    cudaGetSymbolAddress((void**)&WT, g_WT);

    // --- weight transposes ---
    trans(wx_f0, WT, OFF_XF0, 24, 192, 0, 192);
    trans(wx_b0, WT, OFF_XB0, 24, 192, 0, 192);
    trans(wh_f0, WT, OFF_ZRF0, 64, 192, 0, 128);
    trans(wh_b0, WT, OFF_ZRB0, 64, 192, 0, 128);
    trans(wh_f0, WT, OFF_HF0, 64, 192, 128, 64);
    trans(wh_b0, WT, OFF_HB0, 64, 192, 128, 64);
    trans(wx_f1, WT, OFF_XF1, 128, 192, 0, 192);
    trans(wx_b1, WT, OFF_XB1, 128, 192, 0, 192);
    trans(wh_f1, WT, OFF_ZRF1, 64, 192, 0, 128);
    trans(wh_b1, WT, OFF_ZRB1, 64, 192, 0, 128);
    trans(wh_f1, WT, OFF_HF1, 64, 192, 128, 64);
    trans(wh_b1, WT, OFF_HB1, 64, 192, 128, 64);
    trans(w_conv1, WT, OFF_C1, 256, 32, 0, 32);

    // --- input padding + halo zeroing ---
    {
        long n = (long)NIMG_ * PP_ * 24;
        pad_x_k<<<(unsigned)((n + 255) / 256), 256>>>(x, Xpad);
    }
    halo_zero_k<<<(NIMG_ * 132 * 128 + 255) / 256, 256>>>(Y0, NIMG_, 128);
    halo_zero_k<<<(NIMG_ * 132 * 128 + 255) / 256, 256>>>(Y1, NIMG_, 128);
    halo_zero_k<<<(32 * 132 * 64 + 255) / 256, 256>>>(RH, 32, 64);
    halo_zero_k<<<(NIMG_ * 132 * 256 + 255) / 256, 256>>>(XC, NIMG_, 256);

    // --- layer 0 ---
    conv_gates_k<12, 24><<<dim3(4, 4, 2 * NIMG_ * 3), 256>>>(
        Xpad, (long)PP_ * 24, WT + OFF_XF0, WT + OFF_XB0, b_f0, b_b0, XG);
    run_layer(XG, Y0, Z, RH, WT, OFF_ZRF0, OFF_ZRB0, OFF_HF0, OFF_HB0);

    // --- layer 1 ---
    conv_gates_k<64, 128><<<dim3(4, 4, 2 * NIMG_ * 3), 256>>>(
        Y0, (long)PP_ * 128, WT + OFF_XF1, WT + OFF_XB1, b_f1, b_b1, XG);
    run_layer(XG, Y1, Z, RH, WT, OFF_ZRF1, OFF_ZRB1, OFF_HF1, OFF_HB1);

    // --- xr = Y0+Y1, xc = [xr, Y0] ---
    {
        long n = (long)NIMG_ * 1024 * 64;
        addconcat_k<<<(unsigned)((n + 255) / 256), 256>>>(Y0, Y1, XC);
    }

    // --- conv1 + 1x1 + relu ---
    conv1_out_k<<<dim3(4, 4, NIMG_), 256>>>(XC, WT + OFF_C1, b_conv1, w_out, b_out,
                                            (float*)d_out);
}

// round 4
// speedup vs baseline: 2.6733x; 1.1117x over previous
#include <cuda_runtime.h>
#include <math.h>

// ---------------------------------------------------------------------------
// SimpleConvGRU on GB300 — round 3: SMEM-staged activations + packed f32x2.
// Each conv block stages its 10x10xCin padded input tile into shared memory
// (coalesced), then the inner loop uses broadcast LDS (lane-uniform address,
// immediate offsets) + packed fma.rn.f32x2. Weights via LDG (L1-resident).
// This removes the LSU-issue bottleneck (0.67 LDG/cyc demand vs 0.55 floor).
// ---------------------------------------------------------------------------

typedef unsigned long long ull;

#define B_ 16
#define T_ 28
#define NIMG_ 448            // B*T
#define PP_ 1156             // 34*34 padded pixels

// ---------------- device scratch (zero-initialized at load) ----------------
__device__ float g_Xpad[(size_t)NIMG_ * PP_ * 24];
__device__ float g_XG[(size_t)2 * NIMG_ * 1024 * 192];   // unpadded gates
__device__ float g_Y0[(size_t)NIMG_ * PP_ * 128];        // padded
__device__ float g_Y1[(size_t)NIMG_ * PP_ * 128];        // padded
__device__ float g_RH[(size_t)32 * PP_ * 64];            // padded
__device__ float g_Z [(size_t)32 * 1024 * 64];           // unpadded
__device__ float g_XC[(size_t)NIMG_ * PP_ * 256];        // padded
__device__ float g_WT[1041408];                          // transposed weights

// transposed-weight offsets (floats)
#define OFF_XF0   0
#define OFF_XB0   41472
#define OFF_ZRF0  82944
#define OFF_ZRB0  156672
#define OFF_HF0   230400
#define OFF_HB0   267264
#define OFF_XF1   304128
#define OFF_XB1   525312
#define OFF_ZRF1  746496
#define OFF_ZRB1  820224
#define OFF_HF1   893952
#define OFF_HB1   930816
#define OFF_C1    967680

// ---------------- packed f32x2 helpers ----------------
__device__ __forceinline__ void fma2(ull& d, ull a, ull b) {
    asm("fma.rn.f32x2 %0, %1, %2, %0;" : "+l"(d) : "l"(a), "l"(b));
}
__device__ __forceinline__ float red2(ull a) {
    float lo, hi;
    asm("mov.b64 {%0,%1}, %2;" : "=f"(lo), "=f"(hi) : "l"(a));
    return lo + hi;
}
__device__ __forceinline__ float sigm(float x) { return 1.0f / (1.0f + expf(-x)); }

// ---------------------------------------------------------------------------
// Cooperative tile stage: 10 rows x 10 cols x CINH cin-pairs into SMEM.
// gBase points at float offset ((tileRow0)*34 + tileCol0)*CSTRIDE.
// ---------------------------------------------------------------------------
template<int CINH, int CSTRIDE>
__device__ __forceinline__ void stage_tile(const float* __restrict__ gBase, ull* s)
{
    constexpr int TOT = 100 * CINH;
#pragma unroll 4
    for (int i = threadIdx.x; i < TOT; i += 256) {
        int r   = i / (10 * CINH);
        int rem = i - r * (10 * CINH);
        int c   = rem / CINH;
        int cp  = rem - c * CINH;
        s[i] = *(const ull*)(gBase + (long)(r * 34 + c) * CSTRIDE + 2 * cp);
    }
}

// ---------------------------------------------------------------------------
// Core: 3x3 conv from a staged SMEM tile. One warp = 1 output row x 8 px x
// NC*32 couts (lane -> cout). Accumulates (even,odd) cin partials in f32x2.
// sW = smem + warp*10*CINH (ull units). wt layout: [9][CINH][WCO][2] floats.
// ---------------------------------------------------------------------------
template<int CINH, int WCO, int NC>
__device__ __forceinline__ void conv_core_s(
    const ull* sW, const float* __restrict__ wt, int coutIdx, ull acc[NC][8])
{
#pragma unroll
    for (int nc = 0; nc < NC; nc++)
#pragma unroll
        for (int p = 0; p < 8; p++) acc[nc][p] = 0ull;

    const float* wP = wt + coutIdx * 2;

#pragma unroll 1
    for (int cp = 0; cp < CINH; cp++) {
#pragma unroll
        for (int ky = 0; ky < 3; ky++) {
            ull v[10];
#pragma unroll
            for (int q = 0; q < 10; q++)
                v[q] = sW[(ky * 10 + q) * CINH + cp];
#pragma unroll
            for (int kx = 0; kx < 3; kx++) {
#pragma unroll
                for (int nc = 0; nc < NC; nc++) {
                    ull w = *(const ull*)(wP + ((ky * 3 + kx) * CINH * WCO + nc * 32) * 2);
#pragma unroll
                    for (int p = 0; p < 8; p++)
                        fma2(acc[nc][p], v[p + kx], w);
                }
            }
        }
        wP += WCO * 2;
    }
}

// ---------------------------------------------------------------------------
// Input-gate conv: (x or Y0, both dirs) -> XG (+bias). Cout=192 in 3 groups.
// grid = (4, 4, 2*448*3), block 256.
// ---------------------------------------------------------------------------
template<int CINH, int CSTRIDE>
__global__ __launch_bounds__(256, 2) void conv_gates_k(
    const float* __restrict__ in, long imgStride,
    const float* __restrict__ wtF, const float* __restrict__ wtB,
    const float* __restrict__ bF, const float* __restrict__ bB,
    float* __restrict__ XG)
{
    extern __shared__ ull sdyn[];
    int z = blockIdx.z;
    int dir = z / (NIMG_ * 3);
    int rem = z - dir * (NIMG_ * 3);
    int img = rem / 3, cg = rem - (rem / 3) * 3;
    int lane = threadIdx.x & 31, warp = threadIdx.x >> 5;
    int y  = blockIdx.y * 8 + warp + 1;
    int x0 = blockIdx.x * 8 + 1;
    int co = cg * 64 + lane;

    const float* inImg = in + (long)img * imgStride;
    stage_tile<CINH, CSTRIDE>(inImg + (long)((blockIdx.y * 8) * 34 + blockIdx.x * 8) * CSTRIDE, sdyn);
    __syncthreads();

    ull acc[2][8];
    conv_core_s<CINH, 192, 2>(sdyn + warp * 10 * CINH, dir ? wtB : wtF, co, acc);

    const float* bias = dir ? bB : bF;
    float* xg = XG + (((long)dir * NIMG_ + img) * 1024 + (long)(y - 1) * 32 + (x0 - 1)) * 192;
#pragma unroll
    for (int nc = 0; nc < 2; nc++) {
        int c = co + nc * 32;
        float bv = bias[c];
#pragma unroll
        for (int p = 0; p < 8; p++) xg[p * 192 + c] = red2(acc[nc][p]) + bv;
    }
}

// ---------------------------------------------------------------------------
// Recurrent gate conv (h_prev -> z/r) fused with sigmoid + RH = r*h.
// grid = (4, 4, 64): z = dir*32 + b*2 + cg. cg0 = z gates, cg1 = r gates.
// ---------------------------------------------------------------------------
__global__ __launch_bounds__(256, 2) void conv_gh_zrh_k(
    const float* __restrict__ Y,
    const float* __restrict__ wtF, const float* __restrict__ wtB,
    const float* __restrict__ XG, float* __restrict__ Z, float* __restrict__ RH,
    int tf, int tb)
{
    extern __shared__ ull sdyn[];
    int z = blockIdx.z;
    int dir = z >> 5, b = (z >> 1) & 15, cg = z & 1;
    int lane = threadIdx.x & 31, warp = threadIdx.x >> 5;
    int y  = blockIdx.y * 8 + warp + 1;
    int x0 = blockIdx.x * 8 + 1;
    int t = dir ? tb : tf;
    int tprev = dir ? tb + 1 : tf - 1;

    const float* hbase = Y + (long)(b * T_ + tprev) * PP_ * 128 + (dir ? 64 : 0);
    stage_tile<32, 128>(hbase + (long)((blockIdx.y * 8) * 34 + blockIdx.x * 8) * 128, sdyn);
    __syncthreads();

    ull acc[2][8];
    conv_core_s<32, 128, 2>(sdyn + warp * 10 * 32, dir ? wtB : wtF, cg * 64 + lane, acc);

    const float* xg = XG + (((long)dir * NIMG_ + b * T_ + t) * 1024 + (long)(y - 1) * 32 + (x0 - 1)) * 192;
    if (cg == 0) {
        float* zp = Z + ((long)(dir * 16 + b) * 1024 + (long)(y - 1) * 32 + (x0 - 1)) * 64;
#pragma unroll
        for (int nc = 0; nc < 2; nc++) {
            int c = lane + nc * 32;
#pragma unroll
            for (int p = 0; p < 8; p++)
                zp[p * 64 + c] = sigm(xg[p * 192 + c] + red2(acc[nc][p]));
        }
    } else {
        float* rh = RH + ((long)(dir * 16 + b) * PP_ + (long)y * 34 + x0) * 64;
#pragma unroll
        for (int nc = 0; nc < 2; nc++) {
            int c = lane + nc * 32;
#pragma unroll
            for (int p = 0; p < 8; p++) {
                float r = sigm(xg[p * 192 + 64 + c] + red2(acc[nc][p]));
                float h = hbase[((long)y * 34 + x0 + p) * 128 + c];
                rh[p * 64 + c] = r * h;
            }
        }
    }
}

// ---------------------------------------------------------------------------
// Candidate conv (RH -> hh) fused with tanh + GRU blend, writes Y[t].
// grid = (4, 4, 32): z = dir*16 + b.
// ---------------------------------------------------------------------------
__global__ __launch_bounds__(256, 2) void conv_blend_k(
    const float* __restrict__ RH,
    const float* __restrict__ wtF, const float* __restrict__ wtB,
    const float* __restrict__ XG, const float* __restrict__ Z,
    float* __restrict__ Y, int tf, int tb)
{
    extern __shared__ ull sdyn[];
    int z = blockIdx.z;
    int dir = z >> 4, b = z & 15;
    int lane = threadIdx.x & 31, warp = threadIdx.x >> 5;
    int y  = blockIdx.y * 8 + warp + 1;
    int x0 = blockIdx.x * 8 + 1;
    int t = dir ? tb : tf;
    int tprev = dir ? tb + 1 : tf - 1;

    const float* in = RH + (long)(dir * 16 + b) * PP_ * 64;
    stage_tile<32, 64>(in + (long)((blockIdx.y * 8) * 34 + blockIdx.x * 8) * 64, sdyn);
    __syncthreads();

    ull acc[2][8];
    conv_core_s<32, 64, 2>(sdyn + warp * 10 * 32, dir ? wtB : wtF, lane, acc);

    const float* xg = XG + (((long)dir * NIMG_ + b * T_ + t) * 1024 + (long)(y - 1) * 32 + (x0 - 1)) * 192;
    const float* zp = Z + ((long)(dir * 16 + b) * 1024 + (long)(y - 1) * 32 + (x0 - 1)) * 64;
    const float* hprev = Y + (long)(b * T_ + tprev) * PP_ * 128 + (dir ? 64 : 0);
    float* yout = Y + (long)(b * T_ + t) * PP_ * 128 + (dir ? 64 : 0);
#pragma unroll
    for (int nc = 0; nc < 2; nc++) {
        int c = lane + nc * 32;
#pragma unroll
        for (int p = 0; p < 8; p++) {
            float cand = tanhf(xg[p * 192 + 128 + c] + red2(acc[nc][p]));
            float zv = zp[p * 64 + c];
            float hv = hprev[((long)y * 34 + x0 + p) * 128 + c];
            yout[((long)y * 34 + x0 + p) * 128 + c] = zv * hv + (1.0f - zv) * cand;
        }
    }
}

// ---------------------------------------------------------------------------
// conv1 (256->32) fused with the 1x1 head + ReLU (warp-shuffle reduce).
// grid = (4, 4, 448). NC=1 (Cout=32 = one lane group).
// ---------------------------------------------------------------------------
__global__ __launch_bounds__(256, 2) void conv1_out_k(
    const float* __restrict__ XC, const float* __restrict__ wt,
    const float* __restrict__ bc, const float* __restrict__ wo,
    const float* __restrict__ bo, float* __restrict__ out)
{
    extern __shared__ ull sdyn[];
    int img = blockIdx.z;
    int lane = threadIdx.x & 31, warp = threadIdx.x >> 5;
    int y  = blockIdx.y * 8 + warp + 1;
    int x0 = blockIdx.x * 8 + 1;

    const float* inImg = XC + (long)img * PP_ * 256;
    stage_tile<128, 256>(inImg + (long)((blockIdx.y * 8) * 34 + blockIdx.x * 8) * 256, sdyn);
    __syncthreads();

    ull acc[1][8];
    conv_core_s<128, 32, 1>(sdyn + warp * 10 * 128, wt, lane, acc);

    float bv = bc[lane], wv = wo[lane], bov = bo[0];
    float* o = out + (long)img * 1024 + (long)(y - 1) * 32 + (x0 - 1);
#pragma unroll
    for (int p = 0; p < 8; p++) {
        float s = (red2(acc[0][p]) + bv) * wv;
        s += __shfl_xor_sync(0xffffffffu, s, 16);
        s += __shfl_xor_sync(0xffffffffu, s, 8);
        s += __shfl_xor_sync(0xffffffffu, s, 4);
        s += __shfl_xor_sync(0xffffffffu, s, 2);
        s += __shfl_xor_sync(0xffffffffu, s, 1);
        if (lane == 0) o[p] = fmaxf(s + bov, 0.0f);
    }
}

// ---------------------------------------------------------------------------
// t=0 step (h_prev = 0): y = (1-sig(xg_z)) * tanh(xg_h), elementwise.
// ---------------------------------------------------------------------------
__global__ __launch_bounds__(256) void zrh0_k(const float* __restrict__ XG,
                                              float* __restrict__ Y)
{
    int i = blockIdx.x * 256 + threadIdx.x;   // 2*16*1024*64
    int c = i & 63;
    int t1 = i >> 6;
    int pix = t1 & 1023;
    int t2 = t1 >> 10;
    int b = t2 & 15, dir = t2 >> 4;
    int t = dir ? T_ - 1 : 0;
    const float* xg = XG + (((long)dir * NIMG_ + b * T_ + t) * 1024 + pix) * 192;
    float zv = sigm(xg[c]);
    float yv = (1.0f - zv) * tanhf(xg[128 + c]);
    int yy = pix >> 5, xx = pix & 31;
    Y[((long)(b * T_ + t) * PP_ + (long)(yy + 1) * 34 + xx + 1) * 128 + dir * 64 + c] = yv;
}

// ---------------------------------------------------------------------------
// Small utility kernels
// ---------------------------------------------------------------------------
__global__ __launch_bounds__(256) void transpose_w_k(
    const float* __restrict__ src, float* __restrict__ dst,
    int CIN, int COsrc, int o0, int WCO)
{
    int n = 9 * (CIN / 2) * WCO;
    int i = blockIdx.x * 256 + threadIdx.x;
    if (i >= n) return;
    int co = i % WCO;
    int r = i / WCO;
    int cp = r % (CIN / 2);
    int tap = r / (CIN / 2);
    dst[(long)i * 2 + 0] = src[((long)tap * CIN + 2 * cp) * COsrc + o0 + co];
    dst[(long)i * 2 + 1] = src[((long)tap * CIN + 2 * cp + 1) * COsrc + o0 + co];
}

__global__ __launch_bounds__(256) void pad_x_k(const float* __restrict__ x,
                                               float* __restrict__ xp)
{
    long i = (long)blockIdx.x * 256 + threadIdx.x;   // 448*1156*24
    if (i >= (long)NIMG_ * PP_ * 24) return;
    int c = (int)(i % 24);
    long r = i / 24;
    int pix = (int)(r % PP_);
    long img = r / PP_;
    int y = pix / 34, xx = pix % 34;
    float v = 0.0f;
    if (y >= 1 && y <= 32 && xx >= 1 && xx <= 32)
        v = x[(((long)img * 32 + y - 1) * 32 + xx - 1) * 24 + c];
    xp[i] = v;
}

__global__ __launch_bounds__(256) void halo_zero_k(float* __restrict__ p, int nImg, int C)
{
    long i = (long)blockIdx.x * 256 + threadIdx.x;
    long tot = (long)nImg * 132 * C;
    if (i >= tot) return;
    int c = (int)(i % C);
    long r = i / C;
    int hidx = (int)(r % 132);
    long img = r / 132;
    int y, x;
    if (hidx < 34)       { y = 0;  x = hidx; }
    else if (hidx < 68)  { y = 33; x = hidx - 34; }
    else if (hidx < 100) { y = hidx - 68 + 1;  x = 0; }
    else                 { y = hidx - 100 + 1; x = 33; }
    p[((long)img * PP_ + (long)y * 34 + x) * C + c] = 0.0f;
}

__global__ __launch_bounds__(256) void addconcat_k(
    const float* __restrict__ Y0, const float* __restrict__ Y1,
    float* __restrict__ XC)
{
    long i = (long)blockIdx.x * 256 + threadIdx.x;   // 448*1024*64 float4 units
    if (i >= (long)NIMG_ * 1024 * 64) return;
    int cq = (int)(i & 63);
    long r = i >> 6;
    int pix = (int)(r & 1023);
    long img = r >> 10;
    int c = cq * 4;
    int y = pix >> 5, xx = pix & 31;
    long pp = (long)(y + 1) * 34 + xx + 1;
    float4 v;
    if (c < 128) {
        float4 a = *(const float4*)(Y0 + (img * PP_ + pp) * 128 + c);
        float4 bq = *(const float4*)(Y1 + (img * PP_ + pp) * 128 + c);
        v = make_float4(a.x + bq.x, a.y + bq.y, a.z + bq.z, a.w + bq.w);
    } else {
        v = *(const float4*)(Y0 + (img * PP_ + pp) * 128 + c - 128);
    }
    *(float4*)(XC + (img * PP_ + pp) * 256 + c) = v;
}

// ---------------------------------------------------------------------------
// Host
// ---------------------------------------------------------------------------
static void trans(const float* src, float* WT, long dstOff, int CIN, int COsrc,
                  int o0, int WCO)
{
    int n = 9 * (CIN / 2) * WCO;
    transpose_w_k<<<(n + 255) / 256, 256>>>(src, WT + dstOff, CIN, COsrc, o0, WCO);
}

static void run_layer(const float* XG_, float* Y, float* Z_, float* RH_,
                      const float* WT, long zrF, long zrB, long hF, long hB)
{
    zrh0_k<<<8192, 256>>>(XG_, Y);
    for (int i = 1; i < T_; i++) {
        conv_gh_zrh_k<<<dim3(4, 4, 64), 256, 25600>>>(Y, WT + zrF, WT + zrB, XG_, Z_, RH_,
                                                      i, T_ - 1 - i);
        conv_blend_k<<<dim3(4, 4, 32), 256, 25600>>>(RH_, WT + hF, WT + hB, XG_, Z_, Y,
                                                     i, T_ - 1 - i);
    }
}

extern "C" void kernel_launch(void* const* d_in, const int* in_sizes, int n_in,
                              void* d_out, int out_size)
{
    (void)in_sizes; (void)n_in; (void)out_size;
    const float* x       = (const float*)d_in[0];
    const float* wx_f0   = (const float*)d_in[1];
    const float* wh_f0   = (const float*)d_in[2];
    const float* b_f0    = (const float*)d_in[3];
    const float* wx_b0   = (const float*)d_in[4];
    const float* wh_b0   = (const float*)d_in[5];
    const float* b_b0    = (const float*)d_in[6];
    const float* wx_f1   = (const float*)d_in[7];
    const float* wh_f1   = (const float*)d_in[8];
    const float* b_f1    = (const float*)d_in[9];
    const float* wx_b1   = (const float*)d_in[10];
    const float* wh_b1   = (const float*)d_in[11];
    const float* b_b1    = (const float*)d_in[12];
    const float* w_conv1 = (const float*)d_in[13];
    const float* b_conv1 = (const float*)d_in[14];
    const float* w_out   = (const float*)d_in[15];
    const float* b_out   = (const float*)d_in[16];

    float *Xpad, *XG, *Y0, *Y1, *RH, *Z, *XC, *WT;
    cudaGetSymbolAddress((void**)&Xpad, g_Xpad);
    cudaGetSymbolAddress((void**)&XG, g_XG);
    cudaGetSymbolAddress((void**)&Y0, g_Y0);
    cudaGetSymbolAddress((void**)&Y1, g_Y1);
    cudaGetSymbolAddress((void**)&RH, g_RH);
    cudaGetSymbolAddress((void**)&Z,  g_Z);
    cudaGetSymbolAddress((void**)&XC, g_XC);
    cudaGetSymbolAddress((void**)&WT, g_WT);

    // allow >48KB dynamic smem for the big-tile kernels (idempotent)
    cudaFuncSetAttribute(conv_gates_k<64, 128>,
                         cudaFuncAttributeMaxDynamicSharedMemorySize, 51200);
    cudaFuncSetAttribute(conv1_out_k,
                         cudaFuncAttributeMaxDynamicSharedMemorySize, 102400);

    // --- weight transposes ---
    trans(wx_f0, WT, OFF_XF0, 24, 192, 0, 192);
    trans(wx_b0, WT, OFF_XB0, 24, 192, 0, 192);
    trans(wh_f0, WT, OFF_ZRF0, 64, 192, 0, 128);
    trans(wh_b0, WT, OFF_ZRB0, 64, 192, 0, 128);
    trans(wh_f0, WT, OFF_HF0, 64, 192, 128, 64);
    trans(wh_b0, WT, OFF_HB0, 64, 192, 128, 64);
    trans(wx_f1, WT, OFF_XF1, 128, 192, 0, 192);
    trans(wx_b1, WT, OFF_XB1, 128, 192, 0, 192);
    trans(wh_f1, WT, OFF_ZRF1, 64, 192, 0, 128);
    trans(wh_b1, WT, OFF_ZRB1, 64, 192, 0, 128);
    trans(wh_f1, WT, OFF_HF1, 64, 192, 128, 64);
    trans(wh_b1, WT, OFF_HB1, 64, 192, 128, 64);
    trans(w_conv1, WT, OFF_C1, 256, 32, 0, 32);

    // --- input padding + halo zeroing ---
    {
        long n = (long)NIMG_ * PP_ * 24;
        pad_x_k<<<(unsigned)((n + 255) / 256), 256>>>(x, Xpad);
    }
    halo_zero_k<<<(NIMG_ * 132 * 128 + 255) / 256, 256>>>(Y0, NIMG_, 128);
    halo_zero_k<<<(NIMG_ * 132 * 128 + 255) / 256, 256>>>(Y1, NIMG_, 128);
    halo_zero_k<<<(32 * 132 * 64 + 255) / 256, 256>>>(RH, 32, 64);
    halo_zero_k<<<(NIMG_ * 132 * 256 + 255) / 256, 256>>>(XC, NIMG_, 256);

    // --- layer 0 ---
    conv_gates_k<12, 24><<<dim3(4, 4, 2 * NIMG_ * 3), 256, 9600>>>(
        Xpad, (long)PP_ * 24, WT + OFF_XF0, WT + OFF_XB0, b_f0, b_b0, XG);
    run_layer(XG, Y0, Z, RH, WT, OFF_ZRF0, OFF_ZRB0, OFF_HF0, OFF_HB0);

    // --- layer 1 ---
    conv_gates_k<64, 128><<<dim3(4, 4, 2 * NIMG_ * 3), 256, 51200>>>(
        Y0, (long)PP_ * 128, WT + OFF_XF1, WT + OFF_XB1, b_f1, b_b1, XG);
    run_layer(XG, Y1, Z, RH, WT, OFF_ZRF1, OFF_ZRB1, OFF_HF1, OFF_HB1);

    // --- xr = Y0+Y1, xc = [xr, Y0] ---
    {
        long n = (long)NIMG_ * 1024 * 64;
        addconcat_k<<<(unsigned)((n + 255) / 256), 256>>>(Y0, Y1, XC);
    }

    // --- conv1 + 1x1 + relu ---
    conv1_out_k<<<dim3(4, 4, NIMG_), 256, 102400>>>(XC, WT + OFF_C1, b_conv1, w_out, b_out,
                                                    (float*)d_out);
}